// round 14
// baseline (speedup 1.0000x reference)
#include <cuda_runtime.h>
#include <cuda_bf16.h>

#define BATCH 8
#define SEQ   8192
#define DMODEL 1024
#define NTOK (BATCH * SEQ)
#define FULL 0xFFFFFFFFu

// Scratch: sortable keys per token. Active key = monotone uint transform of
// score (always >= 0x00800000 for finite scores); inactive = 0.
__device__ unsigned int g_keys[NTOK];

// ---------------------------------------------------------------------------
// Kernel 1: scores[b,s] = dot(hidden[b,s,:], w) + bias ; key = sortable(score)
// One warp per token; streams 256 MB of hidden once (HBM-bound, ~6.4 TB/s).
// R9/R12 configuration — protected, do not touch.
// ---------------------------------------------------------------------------
__global__ void __launch_bounds__(256)
score_kernel(const float* __restrict__ hidden,
             const unsigned int* __restrict__ mask,
             const float* __restrict__ w,
             const float* __restrict__ bias)
{
    int warp = (blockIdx.x * blockDim.x + threadIdx.x) >> 5;
    int lane = threadIdx.x & 31;
    if (warp >= NTOK) return;

    const float4* hp = reinterpret_cast<const float4*>(hidden + (size_t)warp * DMODEL);
    const float4* wp = reinterpret_cast<const float4*>(w);

    float acc = 0.0f;
#pragma unroll
    for (int i = 0; i < 8; i++) {
        float4 a = __ldcs(hp + lane + i * 32);   // streaming, evict-first
        float4 c = wp[lane + i * 32];            // hot in L1
        acc += a.x * c.x + a.y * c.y + a.z * c.z + a.w * c.w;
    }
#pragma unroll
    for (int o = 16; o; o >>= 1) acc += __shfl_xor_sync(FULL, acc, o);

    if (lane == 0) {
        float s = acc + bias[0];
        unsigned int u = __float_as_uint(s);
        u = (u & 0x80000000u) ? ~u : (u | 0x80000000u);  // order-preserving
        g_keys[warp] = (mask[warp] != 0u) ? u : 0u;      // inactive -> 0
    }
}

// ---------------------------------------------------------------------------
// Kernel 2: per-row exact variable top-k, stable lowest-index tie break.
// ONE histogram pass (bits [31:21], 2048 bins, 4-way interleaved copies),
// register-resident suffix/pick, then candidate compaction of the boundary
// bin + a single-warp 21-bit radix descent (__reduce_add_sync, no block
// barriers) for the exact threshold. 9 __syncthreads total.
// ---------------------------------------------------------------------------
__global__ void __launch_bounds__(1024)
select_kernel(float* __restrict__ out)
{
    __shared__ int hist[2048 * 4];   // pass-1 hist; later overlaid by cand list
    __shared__ int wsum[32];
    __shared__ int sb_bin0;          // count of bin 0 (inactive keys)
    __shared__ int sb_b1;            // boundary bin
    __shared__ int sb_krem;          // rank remainder within boundary bin
    __shared__ int sb_cnt;           // candidate compaction counter
    __shared__ unsigned int sb_t;    // final threshold key
    __shared__ int sb_mneed;         // equals to admit

    const int b = blockIdx.x, tid = threadIdx.x;
    const int lane = tid & 31, wid = tid >> 5;
    const unsigned int* keys = g_keys + b * SEQ;
    float* o = out + b * SEQ;

    // Contiguous ownership: indices [tid*8, tid*8+8)
    const uint4 k0 = reinterpret_cast<const uint4*>(keys)[tid * 2];
    const uint4 k1 = reinterpret_cast<const uint4*>(keys)[tid * 2 + 1];
    unsigned int v[8] = {k0.x, k0.y, k0.z, k0.w, k1.x, k1.y, k1.z, k1.w};

    // ---- zero hist (2 STS.128/thread) + counter ----
    {
        int4* h4 = reinterpret_cast<int4*>(hist);
        int4 z4 = make_int4(0, 0, 0, 0);
        h4[tid] = z4;
        h4[tid + 1024] = z4;
    }
    if (tid == 0) sb_cnt = 0;
    __syncthreads();                                        // S1

    // ---- histogram: bits [31:21], 4 interleaved copies ----
    const int copy = wid & 3;
#pragma unroll
    for (int i = 0; i < 8; i++)
        atomicAdd(&hist[(v[i] >> 21) * 4 + copy], 1);
    __syncthreads();                                        // S2

    // ---- merge copies + block suffix scan, all in registers ----
    const int base = 2047 - tid * 2;   // owns bins {base, base-1}
    int4 c0 = reinterpret_cast<int4*>(hist)[base];
    int4 c1 = reinterpret_cast<int4*>(hist)[base - 1];
    const int h_hi = c0.x + c0.y + c0.z + c0.w;   // count(bin base)
    const int h_lo = c1.x + c1.y + c1.z + c1.w;   // count(bin base-1)
    const int local = h_hi + h_lo;

    int s = local;
#pragma unroll
    for (int d = 1; d < 32; d <<= 1) {
        int n2 = __shfl_up_sync(FULL, s, d);
        if (lane >= d) s += n2;
    }
    if (lane == 31) wsum[wid] = s;
    if (tid == 1023) sb_bin0 = h_lo;   // thread 1023 owns bins {1,0}
    __syncthreads();                                        // S3
    if (wid == 0) {
        int x = wsum[lane];
#pragma unroll
        for (int d = 1; d < 32; d <<= 1) {
            int n2 = __shfl_up_sync(FULL, x, d);
            if (lane >= d) x += n2;
        }
        wsum[lane] = x;
    }
    __syncthreads();                                        // S4

    // Total keys is exactly SEQ; bin 0 holds only inactive keys.
    const int n_active = SEQ - sb_bin0;
    if (n_active == 0) {
        float4 z = make_float4(0.f, 0.f, 0.f, 0.f);
        reinterpret_cast<float4*>(o)[tid * 2]     = z;
        reinterpret_cast<float4*>(o)[tid * 2 + 1] = z;
        return;
    }
    const int k = (n_active + 1) >> 1;   // max(1, ceil(n/2)), n >= 1

    // Register-resident pick: suffix(base) = rex + h_hi, etc.
    {
        const int rex = s - local + ((wid > 0) ? wsum[wid - 1] : 0);
        const int S0 = rex + h_hi;
        if (rex < k && S0 >= k)            { sb_b1 = base;     sb_krem = k - rex; }
        if (S0 < k && S0 + h_lo >= k)      { sb_b1 = base - 1; sb_krem = k - S0;  }
    }
    __syncthreads();                                        // S5
    const int b1 = sb_b1;
    const int krem = sb_krem;

    // ---- compact boundary-bin candidates (overlay hist; order irrelevant) --
    unsigned int* list = reinterpret_cast<unsigned int*>(hist);
#pragma unroll
    for (int i = 0; i < 8; i++)
        if ((int)(v[i] >> 21) == b1) {
            int p = atomicAdd(&sb_cnt, 1);
            list[p] = v[i];
        }
    __syncthreads();                                        // S6

    // ---- warp 0: exact krem-th largest among candidates (21-bit radix,
    //      no block barriers) ----
    if (wid == 0) {
        const int C = sb_cnt;
        unsigned int pfx = 0;
        int rem = krem;
#pragma unroll 1
        for (int bit = 20; bit >= 0; bit--) {
            const unsigned int himask = (~((1u << bit) - 1u)) & 0x1FFFFFu;
            const unsigned int want = pfx | (1u << bit);
            int c1n = 0;
            for (int j = lane; j < C; j += 32) {
                unsigned int low = list[j] & 0x1FFFFFu;
                c1n += ((low & himask) == want);
            }
            c1n = __reduce_add_sync(FULL, c1n);
            if (rem <= c1n) pfx = want;
            else            rem -= c1n;
        }
        if (lane == 0) {
            sb_t = (((unsigned int)b1) << 21) | pfx;
            // Radix invariant: residual rem == krem - #(cand > t) == number
            // of equal-valued keys to admit (lowest index first).
            sb_mneed = rem;
        }
    }
    __syncthreads();                                        // S7
    const unsigned int t = sb_t;
    const int mneed = sb_mneed;

    // ---- stable rank among equals: exclusive block scan (thread order ==
    //      index order thanks to contiguous ownership) ----
    int le = 0;
#pragma unroll
    for (int i = 0; i < 8; i++) le += (v[i] == t);
    int se = le;
#pragma unroll
    for (int d = 1; d < 32; d <<= 1) {
        int n2 = __shfl_up_sync(FULL, se, d);
        if (lane >= d) se += n2;
    }
    if (lane == 31) wsum[wid] = se;
    __syncthreads();                                        // S8
    if (wid == 0) {
        int x = wsum[lane];
#pragma unroll
        for (int d = 1; d < 32; d <<= 1) {
            int n2 = __shfl_up_sync(FULL, x, d);
            if (lane >= d) x += n2;
        }
        wsum[lane] = x;
    }
    __syncthreads();                                        // S9
    int eq_rank = se - le + ((wid > 0) ? wsum[wid - 1] : 0);

    // ---- emit keep mask as float 1.0/0.0 ----
    float r8[8];
#pragma unroll
    for (int i = 0; i < 8; i++) {
        bool keep;
        if (v[i] > t)       keep = true;
        else if (v[i] == t) { keep = (eq_rank < mneed); eq_rank++; }
        else                keep = false;
        r8[i] = keep ? 1.0f : 0.0f;
    }
    reinterpret_cast<float4*>(o)[tid * 2]     = make_float4(r8[0], r8[1], r8[2], r8[3]);
    reinterpret_cast<float4*>(o)[tid * 2 + 1] = make_float4(r8[4], r8[5], r8[6], r8[7]);
}

extern "C" void kernel_launch(void* const* d_in, const int* in_sizes, int n_in,
                              void* d_out, int out_size)
{
    // Bind inputs by element count (all distinct):
    //   hidden 67108864, mask 65536, w 1024, bias 1
    const float*        hidden = nullptr;
    const unsigned int* mask   = nullptr;
    const float*        w      = nullptr;
    const float*        bias   = nullptr;
    for (int i = 0; i < n_in; i++) {
        if      (in_sizes[i] == 67108864) hidden = (const float*)d_in[i];
        else if (in_sizes[i] == 65536)    mask   = (const unsigned int*)d_in[i];
        else if (in_sizes[i] == 1024)     w      = (const float*)d_in[i];
        else if (in_sizes[i] == 1)        bias   = (const float*)d_in[i];
    }
    float* out = (float*)d_out;

    score_kernel<<<NTOK / 8, 256>>>(hidden, mask, w, bias);
    select_kernel<<<BATCH, 1024>>>(out);
}

// round 15
// speedup vs baseline: 1.0426x; 1.0426x over previous
#include <cuda_runtime.h>
#include <cuda_bf16.h>

#define BATCH 8
#define SEQ   8192
#define DMODEL 1024
#define NTOK (BATCH * SEQ)
#define FULL 0xFFFFFFFFu

// Scratch: sortable keys per token. Active key = monotone uint transform of
// score (always >= 0x00800000 for finite scores); inactive = 0.
__device__ unsigned int g_keys[NTOK];

// ---------------------------------------------------------------------------
// Kernel 1: scores[b,s] = dot(hidden[b,s,:], w) + bias ; key = sortable(score)
// One warp per token; streams 256 MB of hidden once (HBM-bound, ~6.3 TB/s).
// R9/R12 configuration — protected, do not touch.
// ---------------------------------------------------------------------------
__global__ void __launch_bounds__(256)
score_kernel(const float* __restrict__ hidden,
             const unsigned int* __restrict__ mask,
             const float* __restrict__ w,
             const float* __restrict__ bias)
{
    int warp = (blockIdx.x * blockDim.x + threadIdx.x) >> 5;
    int lane = threadIdx.x & 31;
    if (warp >= NTOK) return;

    const float4* hp = reinterpret_cast<const float4*>(hidden + (size_t)warp * DMODEL);
    const float4* wp = reinterpret_cast<const float4*>(w);

    float acc = 0.0f;
#pragma unroll
    for (int i = 0; i < 8; i++) {
        float4 a = __ldcs(hp + lane + i * 32);   // streaming, evict-first
        float4 c = wp[lane + i * 32];            // hot in L1
        acc += a.x * c.x + a.y * c.y + a.z * c.z + a.w * c.w;
    }
#pragma unroll
    for (int o = 16; o; o >>= 1) acc += __shfl_xor_sync(FULL, acc, o);

    if (lane == 0) {
        float s = acc + bias[0];
        unsigned int u = __float_as_uint(s);
        u = (u & 0x80000000u) ? ~u : (u | 0x80000000u);  // order-preserving
        g_keys[warp] = (mask[warp] != 0u) ? u : 0u;      // inactive -> 0
    }
}

// ---------------------------------------------------------------------------
// Kernel 2: per-row exact variable top-k, stable lowest-index tie break.
// ONE histogram pass (bits [31:21], 2048 bins, 4-way interleaved ATOMS
// copies, register-resident suffix/pick), then boundary-bin compaction
// (median-of-N(0,1) bin => C is tiny) + one-shot parallel O(C^2) rank to
// get the exact threshold t and tie-admit count mneed. 9 barriers total,
// no serial sections.
// ---------------------------------------------------------------------------
__global__ void __launch_bounds__(1024)
select_kernel(float* __restrict__ out)
{
    __shared__ int hist[2048 * 4];   // pass-1 hist; later overlaid by cand list
    __shared__ int wsum[32];
    __shared__ int sb_bin0;          // count of bin 0 (inactive keys)
    __shared__ int sb_b1;            // boundary bin
    __shared__ int sb_krem;          // rank remainder within boundary bin
    __shared__ int sb_cnt;           // candidate compaction counter
    __shared__ unsigned int sb_t;    // final threshold key
    __shared__ int sb_mneed;         // equals to admit

    const int b = blockIdx.x, tid = threadIdx.x;
    const int lane = tid & 31, wid = tid >> 5;
    const unsigned int* keys = g_keys + b * SEQ;
    float* o = out + b * SEQ;

    // Contiguous ownership: indices [tid*8, tid*8+8)
    const uint4 k0 = reinterpret_cast<const uint4*>(keys)[tid * 2];
    const uint4 k1 = reinterpret_cast<const uint4*>(keys)[tid * 2 + 1];
    unsigned int v[8] = {k0.x, k0.y, k0.z, k0.w, k1.x, k1.y, k1.z, k1.w};

    // ---- zero hist (2 STS.128/thread) + counter ----
    {
        int4* h4 = reinterpret_cast<int4*>(hist);
        int4 z4 = make_int4(0, 0, 0, 0);
        h4[tid] = z4;
        h4[tid + 1024] = z4;
    }
    if (tid == 0) sb_cnt = 0;
    __syncthreads();                                        // S1

    // ---- histogram: bits [31:21], 4 interleaved copies ----
    const int copy = wid & 3;
#pragma unroll
    for (int i = 0; i < 8; i++)
        atomicAdd(&hist[(v[i] >> 21) * 4 + copy], 1);
    __syncthreads();                                        // S2

    // ---- merge copies + block suffix scan, all in registers ----
    const int base = 2047 - tid * 2;   // owns bins {base, base-1}
    int4 c0 = reinterpret_cast<int4*>(hist)[base];
    int4 c1 = reinterpret_cast<int4*>(hist)[base - 1];
    const int h_hi = c0.x + c0.y + c0.z + c0.w;   // count(bin base)
    const int h_lo = c1.x + c1.y + c1.z + c1.w;   // count(bin base-1)
    const int local = h_hi + h_lo;

    int s = local;
#pragma unroll
    for (int d = 1; d < 32; d <<= 1) {
        int n2 = __shfl_up_sync(FULL, s, d);
        if (lane >= d) s += n2;
    }
    if (lane == 31) wsum[wid] = s;
    if (tid == 1023) sb_bin0 = h_lo;   // thread 1023 owns bins {1,0}
    __syncthreads();                                        // S3
    if (wid == 0) {
        int x = wsum[lane];
#pragma unroll
        for (int d = 1; d < 32; d <<= 1) {
            int n2 = __shfl_up_sync(FULL, x, d);
            if (lane >= d) x += n2;
        }
        wsum[lane] = x;
    }
    __syncthreads();                                        // S4

    // Total keys is exactly SEQ; bin 0 holds only inactive keys.
    const int n_active = SEQ - sb_bin0;
    if (n_active == 0) {
        float4 z = make_float4(0.f, 0.f, 0.f, 0.f);
        reinterpret_cast<float4*>(o)[tid * 2]     = z;
        reinterpret_cast<float4*>(o)[tid * 2 + 1] = z;
        return;
    }
    const int k = (n_active + 1) >> 1;   // max(1, ceil(n/2)), n >= 1

    // Register-resident pick: suffix(base) = rex + h_hi, suffix runs downward.
    {
        const int rex = s - local + ((wid > 0) ? wsum[wid - 1] : 0);  // excl.
        const int S0 = rex + h_hi;
        if (rex < k && S0 >= k)       { sb_b1 = base;     sb_krem = k - rex; }
        if (S0 < k && S0 + h_lo >= k) { sb_b1 = base - 1; sb_krem = k - S0;  }
    }
    __syncthreads();                                        // S5
    const int b1 = sb_b1;
    const int krem = sb_krem;

    // ---- compact boundary-bin candidates (overlay hist; order irrelevant) --
    unsigned int* list = reinterpret_cast<unsigned int*>(hist);
#pragma unroll
    for (int i = 0; i < 8; i++)
        if ((int)(v[i] >> 21) == b1) {
            int p = atomicAdd(&sb_cnt, 1);
            list[p] = v[i];
        }
    __syncthreads();                                        // S6

    // ---- one-shot parallel rank: thread holding candidate i counts
    //      greater/equal over the whole list (lockstep j => LDS broadcast).
    //      The value group containing rank krem satisfies
    //      gt < krem <= gt+eq ; all its holders write identical t/mneed. ----
    {
        const int C = sb_cnt;   // tiny in practice (boundary = median bin)
        for (int i = tid; i < C; i += 1024) {
            const unsigned int me = list[i];
            int gt = 0, eq = 0;
            for (int j = 0; j < C; j++) {
                unsigned int x = list[j];
                gt += (x > me);
                eq += (x == me);
            }
            if (gt < krem && krem <= gt + eq) {
                sb_t = me;
                sb_mneed = krem - gt;
            }
        }
    }
    __syncthreads();                                        // S7
    const unsigned int t = sb_t;
    const int mneed = sb_mneed;

    // ---- stable rank among equals: exclusive block scan (thread order ==
    //      index order thanks to contiguous ownership) ----
    int le = 0;
#pragma unroll
    for (int i = 0; i < 8; i++) le += (v[i] == t);
    int se = le;
#pragma unroll
    for (int d = 1; d < 32; d <<= 1) {
        int n2 = __shfl_up_sync(FULL, se, d);
        if (lane >= d) se += n2;
    }
    if (lane == 31) wsum[wid] = se;
    __syncthreads();                                        // S8
    if (wid == 0) {
        int x = wsum[lane];
#pragma unroll
        for (int d = 1; d < 32; d <<= 1) {
            int n2 = __shfl_up_sync(FULL, x, d);
            if (lane >= d) x += n2;
        }
        wsum[lane] = x;
    }
    __syncthreads();                                        // S9
    int eq_rank = se - le + ((wid > 0) ? wsum[wid - 1] : 0);

    // ---- emit keep mask as float 1.0/0.0 ----
    float r8[8];
#pragma unroll
    for (int i = 0; i < 8; i++) {
        bool keep;
        if (v[i] > t)       keep = true;
        else if (v[i] == t) { keep = (eq_rank < mneed); eq_rank++; }
        else                keep = false;
        r8[i] = keep ? 1.0f : 0.0f;
    }
    reinterpret_cast<float4*>(o)[tid * 2]     = make_float4(r8[0], r8[1], r8[2], r8[3]);
    reinterpret_cast<float4*>(o)[tid * 2 + 1] = make_float4(r8[4], r8[5], r8[6], r8[7]);
}

extern "C" void kernel_launch(void* const* d_in, const int* in_sizes, int n_in,
                              void* d_out, int out_size)
{
    // Bind inputs by element count (all distinct):
    //   hidden 67108864, mask 65536, w 1024, bias 1
    const float*        hidden = nullptr;
    const unsigned int* mask   = nullptr;
    const float*        w      = nullptr;
    const float*        bias   = nullptr;
    for (int i = 0; i < n_in; i++) {
        if      (in_sizes[i] == 67108864) hidden = (const float*)d_in[i];
        else if (in_sizes[i] == 65536)    mask   = (const unsigned int*)d_in[i];
        else if (in_sizes[i] == 1024)     w      = (const float*)d_in[i];
        else if (in_sizes[i] == 1)        bias   = (const float*)d_in[i];
    }
    float* out = (float*)d_out;

    score_kernel<<<NTOK / 8, 256>>>(hidden, mask, w, bias);
    select_kernel<<<BATCH, 1024>>>(out);
}

// round 16
// speedup vs baseline: 1.0618x; 1.0184x over previous
#include <cuda_runtime.h>
#include <cuda_bf16.h>

#define BATCH 8
#define SEQ   8192
#define DMODEL 1024
#define NTOK (BATCH * SEQ)
#define FULL 0xFFFFFFFFu

// Scratch: sortable keys per token. Active key = monotone uint transform of
// score (always >= 0x00800000 for finite scores); inactive = 0.
__device__ unsigned int g_keys[NTOK];

// ---------------------------------------------------------------------------
// Kernel 1: scores[b,s] = dot(hidden[b,s,:], w) + bias ; key = sortable(score)
// One warp per token; streams 256 MB of hidden once (HBM-bound, ~6.2 TB/s,
// at the LTS cap). R9/R12 configuration — protected, do not touch.
// ---------------------------------------------------------------------------
__global__ void __launch_bounds__(256)
score_kernel(const float* __restrict__ hidden,
             const unsigned int* __restrict__ mask,
             const float* __restrict__ w,
             const float* __restrict__ bias)
{
    int warp = (blockIdx.x * blockDim.x + threadIdx.x) >> 5;
    int lane = threadIdx.x & 31;
    if (warp >= NTOK) return;

    const float4* hp = reinterpret_cast<const float4*>(hidden + (size_t)warp * DMODEL);
    const float4* wp = reinterpret_cast<const float4*>(w);

    float acc = 0.0f;
#pragma unroll
    for (int i = 0; i < 8; i++) {
        float4 a = __ldcs(hp + lane + i * 32);   // streaming, evict-first
        float4 c = wp[lane + i * 32];            // hot in L1
        acc += a.x * c.x + a.y * c.y + a.z * c.z + a.w * c.w;
    }
#pragma unroll
    for (int o = 16; o; o >>= 1) acc += __shfl_xor_sync(FULL, acc, o);

    if (lane == 0) {
        float s = acc + bias[0];
        unsigned int u = __float_as_uint(s);
        u = (u & 0x80000000u) ? ~u : (u | 0x80000000u);  // order-preserving
        g_keys[warp] = (mask[warp] != 0u) ? u : 0u;      // inactive -> 0
    }
}

// ---------------------------------------------------------------------------
// Kernel 2: per-row exact variable top-k, stable lowest-index tie break.
// One histogram pass (bits [31:21], 2048 bins, 4-way interleaved ATOMS
// copies, register-resident suffix/pick), warp-aggregated boundary-bin
// compaction, one-shot parallel O(C^2) rank (also yields the global equal
// count so the tie-break scan is skipped when all equals are admitted).
// ---------------------------------------------------------------------------
__global__ void __launch_bounds__(1024)
select_kernel(float* __restrict__ out)
{
    __shared__ int hist[2048 * 4];   // pass-1 hist; later overlaid by cand list
    __shared__ int wsum[32];
    __shared__ int sb_bin0;          // count of bin 0 (inactive keys)
    __shared__ int sb_b1;            // boundary bin
    __shared__ int sb_krem;          // rank remainder within boundary bin
    __shared__ int sb_cnt;           // candidate compaction counter
    __shared__ unsigned int sb_t;    // final threshold key
    __shared__ int sb_mneed;         // equals to admit
    __shared__ int sb_alleq;         // 1 if ALL equal-valued keys are admitted

    const int b = blockIdx.x, tid = threadIdx.x;
    const int lane = tid & 31, wid = tid >> 5;
    const unsigned int* keys = g_keys + b * SEQ;
    float* o = out + b * SEQ;

    // Contiguous ownership: indices [tid*8, tid*8+8)
    const uint4 k0 = reinterpret_cast<const uint4*>(keys)[tid * 2];
    const uint4 k1 = reinterpret_cast<const uint4*>(keys)[tid * 2 + 1];
    unsigned int v[8] = {k0.x, k0.y, k0.z, k0.w, k1.x, k1.y, k1.z, k1.w};

    // ---- zero hist (2 STS.128/thread) + counter ----
    {
        int4* h4 = reinterpret_cast<int4*>(hist);
        int4 z4 = make_int4(0, 0, 0, 0);
        h4[tid] = z4;
        h4[tid + 1024] = z4;
    }
    if (tid == 0) sb_cnt = 0;
    __syncthreads();                                        // S1

    // ---- histogram: bits [31:21], 4 interleaved copies ----
    const int copy = wid & 3;
#pragma unroll
    for (int i = 0; i < 8; i++)
        atomicAdd(&hist[(v[i] >> 21) * 4 + copy], 1);
    __syncthreads();                                        // S2

    // ---- merge copies + block suffix scan, all in registers ----
    const int base = 2047 - tid * 2;   // owns bins {base, base-1}
    int4 c0 = reinterpret_cast<int4*>(hist)[base];
    int4 c1 = reinterpret_cast<int4*>(hist)[base - 1];
    const int h_hi = c0.x + c0.y + c0.z + c0.w;   // count(bin base)
    const int h_lo = c1.x + c1.y + c1.z + c1.w;   // count(bin base-1)
    const int local = h_hi + h_lo;

    int s = local;
#pragma unroll
    for (int d = 1; d < 32; d <<= 1) {
        int n2 = __shfl_up_sync(FULL, s, d);
        if (lane >= d) s += n2;
    }
    if (lane == 31) wsum[wid] = s;
    if (tid == 1023) sb_bin0 = h_lo;   // thread 1023 owns bins {1,0}
    __syncthreads();                                        // S3
    if (wid == 0) {
        int x = wsum[lane];
#pragma unroll
        for (int d = 1; d < 32; d <<= 1) {
            int n2 = __shfl_up_sync(FULL, x, d);
            if (lane >= d) x += n2;
        }
        wsum[lane] = x;
    }
    __syncthreads();                                        // S4

    // Total keys is exactly SEQ; bin 0 holds only inactive keys.
    const int n_active = SEQ - sb_bin0;
    if (n_active == 0) {
        float4 z = make_float4(0.f, 0.f, 0.f, 0.f);
        reinterpret_cast<float4*>(o)[tid * 2]     = z;
        reinterpret_cast<float4*>(o)[tid * 2 + 1] = z;
        return;
    }
    const int k = (n_active + 1) >> 1;   // max(1, ceil(n/2)), n >= 1

    // Register-resident pick: suffix(base) = rex + h_hi, suffix runs downward.
    {
        const int rex = s - local + ((wid > 0) ? wsum[wid - 1] : 0);  // excl.
        const int S0 = rex + h_hi;
        if (rex < k && S0 >= k)       { sb_b1 = base;     sb_krem = k - rex; }
        if (S0 < k && S0 + h_lo >= k) { sb_b1 = base - 1; sb_krem = k - S0;  }
    }
    __syncthreads();                                        // S5
    const int b1 = sb_b1;
    const int krem = sb_krem;

    // ---- warp-aggregated compaction of boundary-bin candidates ----
    unsigned int* list = reinterpret_cast<unsigned int*>(hist);
#pragma unroll
    for (int i = 0; i < 8; i++) {
        bool p = ((int)(v[i] >> 21) == b1);
        unsigned int m = __ballot_sync(FULL, p);
        if (m) {
            int leader = __ffs(m) - 1;
            int pos = 0;
            if (lane == leader) pos = atomicAdd(&sb_cnt, __popc(m));
            pos = __shfl_sync(FULL, pos, leader);
            if (p) list[pos + __popc(m & ((1u << lane) - 1u))] = v[i];
        }
    }
    __syncthreads();                                        // S6

    // ---- one-shot parallel rank: thread holding candidate i counts
    //      greater/equal over the whole list (lockstep j => LDS broadcast).
    //      The value group containing rank krem satisfies gt < krem <= gt+eq;
    //      all its holders write identical results. eq is the GLOBAL equal
    //      count (equal keys share the boundary bin), so mneed==eq means
    //      every equal key is admitted -> tie scan skippable. ----
    {
        const int C = sb_cnt;   // tiny in practice (boundary = median bin)
        for (int i = tid; i < C; i += 1024) {
            const unsigned int me = list[i];
            int gt = 0, eq = 0;
            for (int j = 0; j < C; j++) {
                unsigned int x = list[j];
                gt += (x > me);
                eq += (x == me);
            }
            if (gt < krem && krem <= gt + eq) {
                sb_t = me;
                sb_mneed = krem - gt;
                sb_alleq = (krem - gt) == eq;
            }
        }
    }
    __syncthreads();                                        // S7
    const unsigned int t = sb_t;
    const int mneed = sb_mneed;

    if (sb_alleq) {
        // Fast path (typical: unique threshold value): keep = (key >= t).
        float r8[8];
#pragma unroll
        for (int i = 0; i < 8; i++) r8[i] = (v[i] >= t) ? 1.0f : 0.0f;
        reinterpret_cast<float4*>(o)[tid * 2]     = make_float4(r8[0], r8[1], r8[2], r8[3]);
        reinterpret_cast<float4*>(o)[tid * 2 + 1] = make_float4(r8[4], r8[5], r8[6], r8[7]);
        return;
    }

    // ---- stable rank among equals: exclusive block scan (thread order ==
    //      index order thanks to contiguous ownership) ----
    int le = 0;
#pragma unroll
    for (int i = 0; i < 8; i++) le += (v[i] == t);
    int se = le;
#pragma unroll
    for (int d = 1; d < 32; d <<= 1) {
        int n2 = __shfl_up_sync(FULL, se, d);
        if (lane >= d) se += n2;
    }
    if (lane == 31) wsum[wid] = se;
    __syncthreads();                                        // S8
    if (wid == 0) {
        int x = wsum[lane];
#pragma unroll
        for (int d = 1; d < 32; d <<= 1) {
            int n2 = __shfl_up_sync(FULL, x, d);
            if (lane >= d) x += n2;
        }
        wsum[lane] = x;
    }
    __syncthreads();                                        // S9
    int eq_rank = se - le + ((wid > 0) ? wsum[wid - 1] : 0);

    // ---- emit keep mask as float 1.0/0.0 ----
    float r8[8];
#pragma unroll
    for (int i = 0; i < 8; i++) {
        bool keep;
        if (v[i] > t)       keep = true;
        else if (v[i] == t) { keep = (eq_rank < mneed); eq_rank++; }
        else                keep = false;
        r8[i] = keep ? 1.0f : 0.0f;
    }
    reinterpret_cast<float4*>(o)[tid * 2]     = make_float4(r8[0], r8[1], r8[2], r8[3]);
    reinterpret_cast<float4*>(o)[tid * 2 + 1] = make_float4(r8[4], r8[5], r8[6], r8[7]);
}

extern "C" void kernel_launch(void* const* d_in, const int* in_sizes, int n_in,
                              void* d_out, int out_size)
{
    // Bind inputs by element count (all distinct):
    //   hidden 67108864, mask 65536, w 1024, bias 1
    const float*        hidden = nullptr;
    const unsigned int* mask   = nullptr;
    const float*        w      = nullptr;
    const float*        bias   = nullptr;
    for (int i = 0; i < n_in; i++) {
        if      (in_sizes[i] == 67108864) hidden = (const float*)d_in[i];
        else if (in_sizes[i] == 65536)    mask   = (const unsigned int*)d_in[i];
        else if (in_sizes[i] == 1024)     w      = (const float*)d_in[i];
        else if (in_sizes[i] == 1)        bias   = (const float*)d_in[i];
    }
    float* out = (float*)d_out;

    score_kernel<<<NTOK / 8, 256>>>(hidden, mask, w, bias);
    select_kernel<<<BATCH, 1024>>>(out);
}